// round 9
// baseline (speedup 1.0000x reference)
#include <cuda_runtime.h>
#include <math.h>

#define BB 2048
#define DD 512
#define CC 128
#define TT 151
#define G3 1536    // 3*D
#define ROWS 14    // batch rows per CTA (148 CTAs x 14 = 2072 >= 2048; tail padded)
#define NCTA 148   // one CTA per SM
#define PAIRS 7    // ROWS/2 f32x2 pairs
#define NT 512     // threads per CTA

typedef unsigned long long ull;

// ---------------- device scratch (static globals; no allocation) ----------------
__device__ float g_G[129 * G3];            // gi table: G[c] = embed[c]@W_ih^T + b_ih; row 128 = b_ih (zero start token)
__device__ float g_Wt[DD * G3];            // W_hh transposed: Wt[k][j]
__device__ float g_Wpt[DD * CC];           // W_proj transposed: Wpt[k][c]
__device__ float g_stage[(size_t)BB * TT * CC]; // logits staged [B][T][C], transposed at end

// ---------------- packed f32x2 helpers ----------------
__device__ __forceinline__ void fma2(ull& acc, ull a, ull b) {
    asm("fma.rn.f32x2 %0, %1, %2, %0;" : "+l"(acc) : "l"(a), "l"(b));
}
__device__ __forceinline__ ull pack2(float x, float y) {
    ull r; asm("mov.b64 %0, {%1,%2};" : "=l"(r) : "f"(x), "f"(y)); return r;
}
__device__ __forceinline__ float2 unpack2(ull v) {
    float2 r; asm("mov.b64 {%0,%1}, %2;" : "=f"(r.x), "=f"(r.y) : "l"(v)); return r;
}
// streaming (evict-first) float4 store/load: keeps write-once data from evicting L2-resident weights
__device__ __forceinline__ void st_cs4(float* p, float4 v) {
    asm volatile("st.global.cs.v4.f32 [%0], {%1,%2,%3,%4};"
                 :: "l"(p), "f"(v.x), "f"(v.y), "f"(v.z), "f"(v.w) : "memory");
}
__device__ __forceinline__ float ld_cs(const float* p) {
    float v; asm volatile("ld.global.cs.f32 %0, [%1];" : "=f"(v) : "l"(p)); return v;
}
__device__ __forceinline__ void st_cs(float* p, float v) {
    asm volatile("st.global.cs.f32 [%0], %1;" :: "l"(p), "f"(v) : "memory");
}

// ---------------- precompute: G table ----------------
__global__ void precomp_G(const float* __restrict__ embed,
                          const float* __restrict__ W_ih,
                          const float* __restrict__ b_ih) {
    __shared__ float es[DD];
    int c = blockIdx.x;           // 0..128 (128 = zero start token)
    int tid = threadIdx.x;
    if (c < CC) {
        for (int i = tid; i < DD; i += 256) es[i] = embed[(size_t)c * DD + i];
    }
    __syncthreads();
    for (int j = tid; j < G3; j += 256) {
        float acc = b_ih[j];
        if (c < CC) {
            const float* w = W_ih + (size_t)j * DD;
            float s = 0.f;
            #pragma unroll 4
            for (int k = 0; k < DD; k += 4) {
                float4 w4 = *(const float4*)(w + k);
                s += w4.x * es[k] + w4.y * es[k + 1] + w4.z * es[k + 2] + w4.w * es[k + 3];
            }
            acc += s;
        }
        g_G[(size_t)c * G3 + j] = acc;
    }
}

// ---------------- precompute: transpose W_hh ----------------
__global__ void precomp_Wt(const float* __restrict__ W_hh) {
    int idx = blockIdx.x * 256 + threadIdx.x;     // over 1536*512
    if (idx < G3 * DD) {
        int j = idx / DD;
        int k = idx - j * DD;
        g_Wt[(size_t)k * G3 + j] = W_hh[idx];
    }
}

// ---------------- precompute: transpose W_proj ----------------
__global__ void precomp_Wpt(const float* __restrict__ W_proj) {
    int idx = blockIdx.x * 256 + threadIdx.x;     // over 512*128
    if (idx < DD * CC) {
        int k = idx >> 7;
        int c = idx & 127;
        g_Wpt[idx] = W_proj[(size_t)c * DD + k];
    }
}

// ---------------- persistent fused GRU decode ----------------
// One CTA per SM owns 14 batch rows for the ENTIRE sequence (rows independent).
// smem: hA[512][14] + hB[512][14] (transposed h ping-pong) + lg[16][128].
__global__ __launch_bounds__(NT) void gru_kernel(
    const float* __restrict__ feat,
    const float* __restrict__ b_hh,
    const float* __restrict__ b_proj,
    float* __restrict__ out_tok)     // d_out + B*C*T (float tokens), or null
{
    extern __shared__ float sm[];
    float* hA = sm;                   // [k][14]
    float* hB = sm + DD * ROWS;
    float* lg = sm + 2 * DD * ROWS;   // [16][128] (rows 14,15 scratch)
    __shared__ int tok_s[ROWS];

    const int tid = threadIdx.x;
    const int rb  = blockIdx.x * ROWS;

    // ---- load feat tile transposed into hA (h0 = feat); fake rows (>=BB) -> 0 ----
    #pragma unroll
    for (int i = 0; i < 4; i++) {
        int idx = tid + i * NT;       // need 14*128 = 1792 float4
        if (idx < ROWS * 128) {
            int b  = idx >> 7;
            int kq = idx & 127;
            float4 v = make_float4(0.f, 0.f, 0.f, 0.f);
            if (rb + b < BB)
                v = *(const float4*)(feat + (size_t)(rb + b) * DD + kq * 4);
            int base = (kq * 4) * ROWS + b;
            hA[base]            = v.x;
            hA[base + ROWS]     = v.y;
            hA[base + 2 * ROWS] = v.z;
            hA[base + 3 * ROWS] = v.w;
        }
    }
    if (tid < ROWS) tok_s[tid] = CC;  // x0 = 0 -> G row 128 (= b_ih only)
    __syncthreads();

    // per-thread invariants
    const int d = tid;                              // gh: owns gate dim d
    const float bhr = __ldg(&b_hh[d]);
    const float bhz = __ldg(&b_hh[DD + d]);
    const float bhn = __ldg(&b_hh[2 * DD + d]);
    const int   lc   = tid & 127;                   // logits: owns column lc
    const int   lb0  = (tid >> 7) * 4;              // ... for rows lb0..lb0+3 (group 3 partly scratch)
    const float bpc  = __ldg(&b_proj[lc]);

    for (int t = 0; t < TT; t++) {
        float* cur = (t & 1) ? hB : hA;
        float* nxt = (t & 1) ? hA : hB;

        // ---- gh GEMM: acc[j][b] = sum_k Wt[k][j] * h[k][b], 14 rows as 7 f32x2 pairs ----
        ull ar[PAIRS], az[PAIRS], an[PAIRS];
        #pragma unroll
        for (int p = 0; p < PAIRS; p++) { ar[p] = 0ULL; az[p] = 0ULL; an[p] = 0ULL; }

        const float* wtr = g_Wt + d;
        const float* hrow = cur;
        // 1-deep double-buffered weight prefetch (hides L2 latency even if
        // ptxas under-hoists inside the unrolled window)
        float wr0 = __ldg(&wtr[0]), wz0 = __ldg(&wtr[DD]), wn0 = __ldg(&wtr[2 * DD]);
        wtr += G3;
        #pragma unroll 4
        for (int k = 0; k < DD; k++) {
            float wr1, wz1, wn1;
            if (k < DD - 1) {
                wr1 = __ldg(&wtr[0]);
                wz1 = __ldg(&wtr[DD]);
                wn1 = __ldg(&wtr[2 * DD]);
                wtr += G3;
            }
            ull wr2 = pack2(wr0, wr0);
            ull wz2 = pack2(wz0, wz0);
            ull wn2 = pack2(wn0, wn0);
            #pragma unroll
            for (int p = 0; p < PAIRS; p++) {
                ull h2 = *(const ull*)(hrow + 2 * p);   // LDS.64, warp-broadcast (56B row stride -> 8B aligned)
                fma2(ar[p], wr2, h2);
                fma2(az[p], wz2, h2);
                fma2(an[p], wn2, h2);
            }
            hrow += ROWS;
            wr0 = wr1; wz0 = wz1; wn0 = wn1;
        }

        // ---- gates + h_new ----
        #pragma unroll
        for (int p = 0; p < PAIRS; p++) {
            float2 rr = unpack2(ar[p]);
            float2 zz = unpack2(az[p]);
            float2 nn = unpack2(an[p]);
            #pragma unroll
            for (int l = 0; l < 2; l++) {
                int b = 2 * p + l;
                float accr = l ? rr.y : rr.x;
                float accz = l ? zz.y : zz.x;
                float accn = l ? nn.y : nn.x;
                const float* gi = g_G + (size_t)tok_s[b] * G3;
                float r = 1.f / (1.f + expf(-(__ldg(&gi[d]) + accr + bhr)));
                float z = 1.f / (1.f + expf(-(__ldg(&gi[DD + d]) + accz + bhz)));
                float n = tanhf(__ldg(&gi[2 * DD + d]) + r * (accn + bhn));
                float ho = cur[d * ROWS + b];
                nxt[d * ROWS + b] = (1.f - z) * n + z * ho;
            }
        }
        __syncthreads();   // h_new complete

        // ---- logits GEMM: thread = (col lc, rows lb0..lb0+3); group lb0=12 rows 14,15 = scratch ----
        {
            ull a0 = 0ULL, a1 = 0ULL;
            const float* wp = g_Wpt + lc;
            const float* hr = nxt + lb0;
            #pragma unroll 4
            for (int k = 0; k < DD; k++) {
                float w = __ldg(wp); wp += 128;
                ull w2 = pack2(w, w);
                ull h2a = *(const ull*)(hr);       // rows lb0,lb0+1
                ull h2b = *(const ull*)(hr + 2);   // rows lb0+2,lb0+3 (rows 14,15 read adjacent smem: safe, unused)
                hr += ROWS;
                fma2(a0, w2, h2a);
                fma2(a1, w2, h2b);
            }
            float2 v0 = unpack2(a0);
            float2 v1 = unpack2(a1);
            lg[(lb0    ) * 128 + lc] = v0.x + bpc;
            lg[(lb0 + 1) * 128 + lc] = v0.y + bpc;
            lg[(lb0 + 2) * 128 + lc] = v1.x + bpc;
            lg[(lb0 + 3) * 128 + lc] = v1.y + bpc;
        }
        __syncthreads();   // logits complete

        // ---- stage logits [B][T][C] coalesced, streaming (evict-first: protect L2-resident weights) ----
        if (tid < ROWS * 32) {        // 448 float4 = 14*128
            int b  = tid >> 5;
            int cq = tid & 31;
            if (rb + b < BB) {
                float4 v = *(const float4*)(lg + b * 128 + cq * 4);
                st_cs4(g_stage + ((size_t)(rb + b) * TT + t) * CC + cq * 4, v);
            }
        }

        // ---- parallel argmax (first-max semantics) + token feedback ----
        if (tid < ROWS * 16) {        // 224 threads = 7 full warps
            int row = tid >> 4;
            int l16 = tid & 15;
            const float* lrow = lg + row * 128;
            float best = -3.4e38f;
            int bi = 0;
            #pragma unroll
            for (int j = 0; j < 8; j++) {
                int c = l16 + 16 * j;          // increasing c per thread
                float v = lrow[c];
                if (v > best) { best = v; bi = c; }
            }
            #pragma unroll
            for (int mask = 8; mask >= 1; mask >>= 1) {
                float ob  = __shfl_xor_sync(0xffffffffu, best, mask);
                int   obi = __shfl_xor_sync(0xffffffffu, bi,   mask);
                if (ob > best || (ob == best && obi < bi)) { best = ob; bi = obi; }
            }
            if (l16 == 0) {
                tok_s[row] = bi;               // always 0..127: g_G index stays in-bounds even for fake rows
                if (out_tok && rb + row < BB)
                    out_tok[(size_t)(rb + row) * TT + t] = (float)bi;
            }
        }
        __syncthreads();   // tok_s ready; lg & old cur free for reuse
    }
}

// ---------------- final transpose: stage[B][T][C] -> out[B][C][T] ----------------
__global__ void transpose_kernel(float* __restrict__ out) {
    __shared__ float tile[32][33];
    int b  = blockIdx.z;
    int t0 = blockIdx.x * 32;
    int c0 = blockIdx.y * 32;
    int tx = threadIdx.x, ty = threadIdx.y;   // block (32,8)
    #pragma unroll
    for (int i = 0; i < 4; i++) {
        int t = t0 + ty + i * 8;
        if (t < TT)
            tile[ty + i * 8][tx] = ld_cs(&g_stage[((size_t)b * TT + t) * CC + c0 + tx]);
    }
    __syncthreads();
    #pragma unroll
    for (int i = 0; i < 4; i++) {
        int c = c0 + ty + i * 8;
        int t = t0 + tx;
        if (t < TT)
            st_cs(&out[((size_t)b * CC + c) * TT + t], tile[tx][ty + i * 8]);
    }
}

// ---------------- launch ----------------
extern "C" void kernel_launch(void* const* d_in, const int* in_sizes, int n_in,
                              void* d_out, int out_size) {
    const float* feat   = (const float*)d_in[0];
    const float* W_ih   = (const float*)d_in[1];
    const float* W_hh   = (const float*)d_in[2];
    const float* b_ih   = (const float*)d_in[3];
    const float* b_hh   = (const float*)d_in[4];
    const float* W_proj = (const float*)d_in[5];
    const float* b_proj = (const float*)d_in[6];
    const float* embed  = (const float*)d_in[7];
    float* out = (float*)d_out;

    const int SMEM_BYTES = (2 * DD * ROWS + 16 * CC) * 4;   // 65536
    cudaFuncSetAttribute(gru_kernel, cudaFuncAttributeMaxDynamicSharedMemorySize, SMEM_BYTES);

    // precompute (cheap; replayed each graph iteration)
    precomp_G<<<129, 256>>>(embed, W_ih, b_ih);
    precomp_Wt<<<(G3 * DD + 255) / 256, 256>>>(W_hh);
    precomp_Wpt<<<(DD * CC + 255) / 256, 256>>>(W_proj);

    const long long expected = (long long)BB * CC * TT + (long long)BB * TT;
    float* out_tok = ((long long)out_size >= expected) ? out + (size_t)BB * CC * TT : nullptr;

    // persistent kernel: whole T loop inside, one CTA per SM
    gru_kernel<<<NCTA, NT, SMEM_BYTES>>>(feat, b_hh, b_proj, out_tok);

    dim3 tb(32, 8);
    dim3 tg((TT + 31) / 32, CC / 32, BB);
    transpose_kernel<<<tg, tb>>>(out);
}

// round 11
// speedup vs baseline: 1.4147x; 1.4147x over previous
#include <cuda_runtime.h>
#include <math.h>

#define BB 2048
#define DD 512
#define CC 128
#define TT 151
#define G3 1536    // 3*D
#define ROWS 14    // batch rows per CTA (148 CTAs x 14 = 2072 >= 2048; tail padded)
#define NCTA 148   // one CTA per SM
#define PAIRS 7    // ROWS/2 f32x2 pairs
#define NT 512     // threads per CTA

typedef unsigned long long ull;

// ---------------- device scratch (static globals; no allocation) ----------------
__device__ float  g_G[129 * G3];               // gi table: G[c] = embed[c]@W_ih^T + b_ih; row 128 = b_ih (zero start)
__device__ float4 g_W4[(DD / 4) * G3];         // W_hh transposed + k-packed: g_W4[kq*G3+j] = (Wt[4kq][j]..Wt[4kq+3][j])
__device__ float4 g_Wp4[(DD / 4) * CC];        // W_proj transposed + k-packed: g_Wp4[kq*CC+c] = (Wpt[4kq][c]..)
__device__ float  g_stage[(size_t)BB * TT * CC]; // logits staged [B][T][C], transposed at end

// ---------------- packed f32x2 helpers ----------------
__device__ __forceinline__ void fma2(ull& acc, ull a, ull b) {
    asm("fma.rn.f32x2 %0, %1, %2, %0;" : "+l"(acc) : "l"(a), "l"(b));
}
__device__ __forceinline__ ull pack2(float x, float y) {
    ull r; asm("mov.b64 %0, {%1,%2};" : "=l"(r) : "f"(x), "f"(y)); return r;
}
__device__ __forceinline__ float2 unpack2(ull v) {
    float2 r; asm("mov.b64 {%0,%1}, %2;" : "=f"(r.x), "=f"(r.y) : "l"(v)); return r;
}
// streaming (evict-first) stores/loads for write-once data (protect L2-resident weights)
__device__ __forceinline__ void st_cs4(float* p, float4 v) {
    asm volatile("st.global.cs.v4.f32 [%0], {%1,%2,%3,%4};"
                 :: "l"(p), "f"(v.x), "f"(v.y), "f"(v.z), "f"(v.w) : "memory");
}
__device__ __forceinline__ float ld_cs(const float* p) {
    float v; asm volatile("ld.global.cs.f32 %0, [%1];" : "=f"(v) : "l"(p)); return v;
}
__device__ __forceinline__ void st_cs(float* p, float v) {
    asm volatile("st.global.cs.f32 [%0], %1;" :: "l"(p), "f"(v) : "memory");
}
// constant-index float4 component (folds under full unroll)
__device__ __forceinline__ float f4c(float4 v, int kk) {
    return kk == 0 ? v.x : kk == 1 ? v.y : kk == 2 ? v.z : v.w;
}

// ---------------- precompute: G table ----------------
__global__ void precomp_G(const float* __restrict__ embed,
                          const float* __restrict__ W_ih,
                          const float* __restrict__ b_ih) {
    __shared__ float es[DD];
    int c = blockIdx.x;           // 0..128 (128 = zero start token)
    int tid = threadIdx.x;
    if (c < CC) {
        for (int i = tid; i < DD; i += 256) es[i] = embed[(size_t)c * DD + i];
    }
    __syncthreads();
    for (int j = tid; j < G3; j += 256) {
        float acc = b_ih[j];
        if (c < CC) {
            const float* w = W_ih + (size_t)j * DD;
            float s = 0.f;
            #pragma unroll 4
            for (int k = 0; k < DD; k += 4) {
                float4 w4 = *(const float4*)(w + k);
                s += w4.x * es[k] + w4.y * es[k + 1] + w4.z * es[k + 2] + w4.w * es[k + 3];
            }
            acc += s;
        }
        g_G[(size_t)c * G3 + j] = acc;
    }
}

// ---------------- precompute: W_hh -> transposed, k-packed float4 ----------------
__global__ void precomp_W4(const float* __restrict__ W_hh) {
    int idx = blockIdx.x * 256 + threadIdx.x;     // over (DD/4)*G3 = 196608
    if (idx < (DD / 4) * G3) {
        int kq = idx / G3;
        int j  = idx - kq * G3;
        int k0 = kq * 4;
        const float* wr = W_hh + (size_t)j * DD + k0;   // Wt[k][j] = W_hh[j*DD+k]
        g_W4[idx] = make_float4(wr[0], wr[1], wr[2], wr[3]);
    }
}

// ---------------- precompute: W_proj -> transposed, k-packed float4 ----------------
__global__ void precomp_Wp4(const float* __restrict__ W_proj) {
    int idx = blockIdx.x * 256 + threadIdx.x;     // over (DD/4)*CC = 16384
    if (idx < (DD / 4) * CC) {
        int kq = idx >> 7;
        int c  = idx & 127;
        const float* wr = W_proj + (size_t)c * DD + kq * 4;  // Wpt[k][c] = W_proj[c*DD+k]
        g_Wp4[idx] = make_float4(wr[0], wr[1], wr[2], wr[3]);
    }
}

// ---------------- persistent fused GRU decode ----------------
// One CTA per SM owns 14 batch rows for the ENTIRE sequence (rows independent).
// smem: hA[512][14] + hB[512][14] (transposed h ping-pong) + lg[16][128].
__global__ __launch_bounds__(NT) void gru_kernel(
    const float* __restrict__ feat,
    const float* __restrict__ b_hh,
    const float* __restrict__ b_proj,
    float* __restrict__ out_tok)     // d_out + B*C*T (float tokens), or null
{
    extern __shared__ float sm[];
    float* hA = sm;                   // [k][14]
    float* hB = sm + DD * ROWS;
    float* lg = sm + 2 * DD * ROWS;   // [16][128] (rows 14,15 scratch)
    __shared__ int tok_s[ROWS];

    const int tid = threadIdx.x;
    const int rb  = blockIdx.x * ROWS;

    // ---- load feat tile transposed into hA (h0 = feat); fake rows (>=BB) -> 0 ----
    #pragma unroll
    for (int i = 0; i < 4; i++) {
        int idx = tid + i * NT;       // need 14*128 = 1792 float4
        if (idx < ROWS * 128) {
            int b  = idx >> 7;
            int kq = idx & 127;
            float4 v = make_float4(0.f, 0.f, 0.f, 0.f);
            if (rb + b < BB)
                v = *(const float4*)(feat + (size_t)(rb + b) * DD + kq * 4);
            int base = (kq * 4) * ROWS + b;
            hA[base]            = v.x;
            hA[base + ROWS]     = v.y;
            hA[base + 2 * ROWS] = v.z;
            hA[base + 3 * ROWS] = v.w;
        }
    }
    if (tid < ROWS) tok_s[tid] = CC;  // x0 = 0 -> G row 128 (= b_ih only)
    __syncthreads();

    // per-thread invariants
    const int d = tid;                              // gh: owns gate dim d
    const float bhr = __ldg(&b_hh[d]);
    const float bhz = __ldg(&b_hh[DD + d]);
    const float bhn = __ldg(&b_hh[2 * DD + d]);
    const int   lc   = tid & 127;                   // logits: owns column lc
    const int   lb0  = (tid >> 7) * 4;              // ... for rows lb0..lb0+3 (group 3 partly scratch)
    const float bpc  = __ldg(&b_proj[lc]);

    for (int t = 0; t < TT; t++) {
        float* cur = (t & 1) ? hB : hA;
        float* nxt = (t & 1) ? hA : hB;

        // ---- gh GEMM: acc[j][b] = sum_k Wt[k][j] * h[k][b] ----
        // Weights via float4 k-packs; software pipeline: blocks of 8 k (2 kq),
        // double-buffered, prefetch issued one FULL block ahead (~336-cycle cover > L2 262).
        ull ar[PAIRS], az[PAIRS], an[PAIRS];
        #pragma unroll
        for (int p = 0; p < PAIRS; p++) { ar[p] = 0ULL; az[p] = 0ULL; an[p] = 0ULL; }

        float4 bR[2][2], bZ[2][2], bN[2][2];
        const float4* wbase = g_W4 + d;
        {   // preload block 0 (kq 0,1)
            const float4* w0 = wbase;
            bR[0][0] = __ldg(w0);       bZ[0][0] = __ldg(w0 + DD);       bN[0][0] = __ldg(w0 + 2 * DD);
            const float4* w1 = wbase + G3;
            bR[0][1] = __ldg(w1);       bZ[0][1] = __ldg(w1 + DD);       bN[0][1] = __ldg(w1 + 2 * DD);
        }
        const float* hrow = cur;
        #pragma unroll 2
        for (int blk = 0; blk < 64; blk++) {
            const int cb = blk & 1, nb = cb ^ 1;
            if (blk < 63) {     // prefetch next block (kq = 2blk+2, 2blk+3)
                const float4* w0 = wbase + (size_t)(2 * blk + 2) * G3;
                bR[nb][0] = __ldg(w0);      bZ[nb][0] = __ldg(w0 + DD);      bN[nb][0] = __ldg(w0 + 2 * DD);
                const float4* w1 = w0 + G3;
                bR[nb][1] = __ldg(w1);      bZ[nb][1] = __ldg(w1 + DD);      bN[nb][1] = __ldg(w1 + 2 * DD);
            }
            #pragma unroll
            for (int q = 0; q < 2; q++) {
                #pragma unroll
                for (int kk = 0; kk < 4; kk++) {
                    float wr = f4c(bR[cb][q], kk);
                    float wz = f4c(bZ[cb][q], kk);
                    float wn = f4c(bN[cb][q], kk);
                    ull wr2 = pack2(wr, wr);
                    ull wz2 = pack2(wz, wz);
                    ull wn2 = pack2(wn, wn);
                    #pragma unroll
                    for (int p = 0; p < PAIRS; p++) {
                        ull h2 = *(const ull*)(hrow + 2 * p);   // LDS.64, warp-broadcast
                        fma2(ar[p], wr2, h2);
                        fma2(az[p], wz2, h2);
                        fma2(an[p], wn2, h2);
                    }
                    hrow += ROWS;
                }
            }
        }

        // ---- gates + h_new (gi gathers batched 3-wide so ptxas can front-issue them) ----
        #pragma unroll
        for (int p = 0; p < PAIRS; p++) {
            float2 rr = unpack2(ar[p]);
            float2 zz = unpack2(az[p]);
            float2 nn = unpack2(an[p]);
            const float* gi0 = g_G + (size_t)tok_s[2 * p] * G3;
            const float* gi1 = g_G + (size_t)tok_s[2 * p + 1] * G3;
            float gr0 = __ldg(&gi0[d]), gz0 = __ldg(&gi0[DD + d]), gn0 = __ldg(&gi0[2 * DD + d]);
            float gr1 = __ldg(&gi1[d]), gz1 = __ldg(&gi1[DD + d]), gn1 = __ldg(&gi1[2 * DD + d]);
            {
                int b = 2 * p;
                float r = 1.f / (1.f + expf(-(gr0 + rr.x + bhr)));
                float z = 1.f / (1.f + expf(-(gz0 + zz.x + bhz)));
                float n = tanhf(gn0 + r * (nn.x + bhn));
                float ho = cur[d * ROWS + b];
                nxt[d * ROWS + b] = (1.f - z) * n + z * ho;
            }
            {
                int b = 2 * p + 1;
                float r = 1.f / (1.f + expf(-(gr1 + rr.y + bhr)));
                float z = 1.f / (1.f + expf(-(gz1 + zz.y + bhz)));
                float n = tanhf(gn1 + r * (nn.y + bhn));
                float ho = cur[d * ROWS + b];
                nxt[d * ROWS + b] = (1.f - z) * n + z * ho;
            }
        }
        __syncthreads();   // h_new complete

        // ---- logits GEMM: thread = (col lc, rows lb0..lb0+3); float4 weights, unroll for MLP ----
        {
            ull a0 = 0ULL, a1 = 0ULL;
            const float4* wp4 = g_Wp4 + lc;
            const float* hr = nxt + lb0;
            #pragma unroll 4
            for (int kq = 0; kq < 128; kq++) {
                float4 w4 = __ldg(wp4); wp4 += CC;
                #pragma unroll
                for (int kk = 0; kk < 4; kk++) {
                    float w = f4c(w4, kk);
                    ull w2 = pack2(w, w);
                    ull h2a = *(const ull*)(hr);       // rows lb0,lb0+1
                    ull h2b = *(const ull*)(hr + 2);   // rows lb0+2,lb0+3 (group 3: scratch reads, unused)
                    hr += ROWS;
                    fma2(a0, w2, h2a);
                    fma2(a1, w2, h2b);
                }
            }
            float2 v0 = unpack2(a0);
            float2 v1 = unpack2(a1);
            lg[(lb0    ) * 128 + lc] = v0.x + bpc;
            lg[(lb0 + 1) * 128 + lc] = v0.y + bpc;
            lg[(lb0 + 2) * 128 + lc] = v1.x + bpc;
            lg[(lb0 + 3) * 128 + lc] = v1.y + bpc;
        }
        __syncthreads();   // logits complete

        // ---- stage logits [B][T][C] coalesced, streaming ----
        if (tid < ROWS * 32) {        // 448 float4 = 14*128
            int b  = tid >> 5;
            int cq = tid & 31;
            if (rb + b < BB) {
                float4 v = *(const float4*)(lg + b * 128 + cq * 4);
                st_cs4(g_stage + ((size_t)(rb + b) * TT + t) * CC + cq * 4, v);
            }
        }

        // ---- parallel argmax (first-max semantics) + token feedback ----
        if (tid < ROWS * 16) {        // 224 threads = 7 full warps
            int row = tid >> 4;
            int l16 = tid & 15;
            const float* lrow = lg + row * 128;
            float best = -3.4e38f;
            int bi = 0;
            #pragma unroll
            for (int j = 0; j < 8; j++) {
                int c = l16 + 16 * j;          // increasing c per thread
                float v = lrow[c];
                if (v > best) { best = v; bi = c; }
            }
            #pragma unroll
            for (int mask = 8; mask >= 1; mask >>= 1) {
                float ob  = __shfl_xor_sync(0xffffffffu, best, mask);
                int   obi = __shfl_xor_sync(0xffffffffu, bi,   mask);
                if (ob > best || (ob == best && obi < bi)) { best = ob; bi = obi; }
            }
            if (l16 == 0) {
                tok_s[row] = bi;               // always 0..127: g_G index stays in-bounds even for fake rows
                if (out_tok && rb + row < BB)
                    out_tok[(size_t)(rb + row) * TT + t] = (float)bi;
            }
        }
        __syncthreads();   // tok_s ready; lg & old cur free for reuse
    }
}

// ---------------- final transpose: stage[B][T][C] -> out[B][C][T] ----------------
__global__ void transpose_kernel(float* __restrict__ out) {
    __shared__ float tile[32][33];
    int b  = blockIdx.z;
    int t0 = blockIdx.x * 32;
    int c0 = blockIdx.y * 32;
    int tx = threadIdx.x, ty = threadIdx.y;   // block (32,8)
    #pragma unroll
    for (int i = 0; i < 4; i++) {
        int t = t0 + ty + i * 8;
        if (t < TT)
            tile[ty + i * 8][tx] = ld_cs(&g_stage[((size_t)b * TT + t) * CC + c0 + tx]);
    }
    __syncthreads();
    #pragma unroll
    for (int i = 0; i < 4; i++) {
        int c = c0 + ty + i * 8;
        int t = t0 + tx;
        if (t < TT)
            st_cs(&out[((size_t)b * CC + c) * TT + t], tile[tx][ty + i * 8]);
    }
}

// ---------------- launch ----------------
extern "C" void kernel_launch(void* const* d_in, const int* in_sizes, int n_in,
                              void* d_out, int out_size) {
    const float* feat   = (const float*)d_in[0];
    const float* W_ih   = (const float*)d_in[1];
    const float* W_hh   = (const float*)d_in[2];
    const float* b_ih   = (const float*)d_in[3];
    const float* b_hh   = (const float*)d_in[4];
    const float* W_proj = (const float*)d_in[5];
    const float* b_proj = (const float*)d_in[6];
    const float* embed  = (const float*)d_in[7];
    float* out = (float*)d_out;

    const int SMEM_BYTES = (2 * DD * ROWS + 16 * CC) * 4;   // 65536
    cudaFuncSetAttribute(gru_kernel, cudaFuncAttributeMaxDynamicSharedMemorySize, SMEM_BYTES);

    // precompute (cheap; replayed each graph iteration)
    precomp_G<<<129, 256>>>(embed, W_ih, b_ih);
    precomp_W4<<<((DD / 4) * G3 + 255) / 256, 256>>>(W_hh);
    precomp_Wp4<<<((DD / 4) * CC + 255) / 256, 256>>>(W_proj);

    const long long expected = (long long)BB * CC * TT + (long long)BB * TT;
    float* out_tok = ((long long)out_size >= expected) ? out + (size_t)BB * CC * TT : nullptr;

    // persistent kernel: whole T loop inside, one CTA per SM
    gru_kernel<<<NCTA, NT, SMEM_BYTES>>>(feat, b_hh, b_proj, out_tok);

    dim3 tb(32, 8);
    dim3 tg((TT + 31) / 32, CC / 32, BB);
    transpose_kernel<<<tg, tb>>>(out);
}